// round 2
// baseline (speedup 1.0000x reference)
#include <cuda_runtime.h>
#include <cuda_bf16.h>
#include <math.h>

// ---------------- problem constants ----------------
#define U_NN   50000
#define I_NN   25000
#define DD     64
#define DT     192        // D*(L+1)
#define RR     2
#define LL     2
#define E_UI   500000
#define E_TR   600000
#define E_II   400000
#define BB     512
#define KK     100
#define EPSV   1e-8f

// ---------------- scratch (static device globals; no runtime alloc) -------
__device__ __align__(16) float g_Uf[U_NN * DT];          // [U,192] concat user feats
__device__ __align__(16) float g_If[I_NN * DT];          // [I,192]
__device__ __align__(16) float g_Sf[RR][I_NN * DT];      // [R][I,192]
__device__ __align__(16) float g_Uagg[U_NN * DD];
__device__ __align__(16) float g_Iagg[I_NN * DD];
__device__ __align__(16) float g_IGagg[RR][I_NN * DD];
__device__            float g_cuser[U_NN * RR];          // ubw/(ubd+eps)
__device__            float g_invig[RR][I_NN];
__device__            int   g_itemcnt[I_NN];
__device__            float g_invdeg[I_NN];
__device__            int   g_u2b[U_NN];
__device__ __align__(16) float g_aggsel[RR][BB * DT];
__device__ __align__(16) float g_G[RR][DT * DT];         // W W^T
__device__ __align__(16) float g_z[RR][BB * DT];

// ---------------- helpers ----------------
__device__ __forceinline__ void red_add_v4(float* p, float x, float y, float z, float w) {
    asm volatile("red.global.add.v4.f32 [%0], {%1,%2,%3,%4};"
                 :: "l"(p), "f"(x), "f"(y), "f"(z), "f"(w) : "memory");
}

__device__ __forceinline__ const float* feat_ptr(int s) {
    switch (s) { case 0: return g_Uf; case 1: return g_If;
                 case 2: return g_Sf[0]; default: return g_Sf[1]; }
}
__device__ __forceinline__ float* feat_ptr_w(int s) {
    switch (s) { case 0: return g_Uf; case 1: return g_If;
                 case 2: return g_Sf[0]; default: return g_Sf[1]; }
}
__device__ __forceinline__ const float* agg_ptr(int s) {
    switch (s) { case 0: return g_Uagg; case 1: return g_Iagg;
                 case 2: return g_IGagg[0]; default: return g_IGagg[1]; }
}
__device__ __forceinline__ float* agg_ptr_w(int s) {
    switch (s) { case 0: return g_Uagg; case 1: return g_Iagg;
                 case 2: return g_IGagg[0]; default: return g_IGagg[1]; }
}

// ---------------- init kernels ----------------
__global__ void k_zero_itemcnt() {
    int t = blockIdx.x * blockDim.x + threadIdx.x;
    if (t < I_NN) g_itemcnt[t] = 0;
}

__global__ void k_coeffs(const int* __restrict__ ubd, const int* __restrict__ igd,
                         const float* __restrict__ mgnn) {
    int t = blockIdx.x * blockDim.x + threadIdx.x;
    if (t < U_NN) {
        float m0 = mgnn[0], m1 = mgnn[1];
        float mx = fmaxf(m0, m1);
        float e0 = expf(m0 - mx), e1 = expf(m1 - mx);
        float inv = 1.0f / (e0 + e1);
        float w0 = e0 * inv, w1 = e1 * inv;
        float d0 = (float)ubd[t * 2 + 0], d1 = (float)ubd[t * 2 + 1];
        float total = d0 * w0 + d1 * w1;
        float itot = 1.0f / (total + EPSV);
        g_cuser[t * 2 + 0] = d0 * w0 * itot / (d0 + EPSV);
        g_cuser[t * 2 + 1] = d1 * w1 * itot / (d1 + EPSV);
    }
    if (t < I_NN) {
        g_invig[0][t] = 1.0f / ((float)igd[0 * I_NN + t] + EPSV);
        g_invig[1][t] = 1.0f / ((float)igd[1 * I_NN + t] + EPSV);
    }
}

__global__ void k_copy_emb(const float* __restrict__ ue, const float* __restrict__ ie) {
    int t = blockIdx.x * blockDim.x + threadIdx.x;
    int nU = U_NN * DD;
    if (t < nU) {
        int u = t >> 6, c = t & 63;
        g_Uf[u * DT + c] = ue[t];
    } else if (t < nU + I_NN * DD) {
        int j = t - nU;
        int i = j >> 6, c = j & 63;
        float v = ie[j];
        g_If[i * DT + c] = v;
        g_Sf[0][i * DT + c] = v;
        g_Sf[1][i * DT + c] = v;
    }
}

__global__ void k_hist(const int* __restrict__ tc) {
    int e = blockIdx.x * blockDim.x + threadIdx.x;
    if (e < E_TR) atomicAdd(&g_itemcnt[tc[e]], 1);
}

__global__ void k_invdeg() {
    int i = blockIdx.x * blockDim.x + threadIdx.x;
    if (i < I_NN) g_invdeg[i] = 1.0f / ((float)g_itemcnt[i] + EPSV);
}

// ---------------- per-layer kernels ----------------
__global__ void k_zero_layer() {
    int t = blockIdx.x * blockDim.x + threadIdx.x;
    int n1 = U_NN * DD, n2 = I_NN * DD;
    if (t < n1) g_Uagg[t] = 0.f;
    else if (t < n1 + n2) g_Iagg[t - n1] = 0.f;
    else if (t < n1 + 2 * n2) g_IGagg[0][t - n1 - n2] = 0.f;
    else if (t < n1 + 3 * n2) g_IGagg[1][t - n1 - 2 * n2] = 0.f;
}

// gather feat[gIdx] * coeff(sIdx) -> red into agg[sIdx]
// coeffSel: 0 = c_user[s*2+r], 1 = invdeg[s], 2 = invig[r][s]
__global__ void k_edge(const int* __restrict__ gI, const int* __restrict__ sI,
                       int nE, int srcSel, int colOff, int dstSel,
                       int coeffSel, int r) {
    int tid = blockIdx.x * blockDim.x + threadIdx.x;
    if (tid >= nE * 16) return;
    int e = tid >> 4, ch = tid & 15;
    int g = gI[e], s = sI[e];
    float coeff;
    if (coeffSel == 0)      coeff = g_cuser[s * 2 + r];
    else if (coeffSel == 1) coeff = g_invdeg[s];
    else                    coeff = g_invig[r][s];
    const float* src = feat_ptr(srcSel) + colOff;
    const float4 v = *reinterpret_cast<const float4*>(src + (long)g * DT + ch * 4);
    float* d = agg_ptr_w(dstSel) + (long)s * DD + ch * 4;
    red_add_v4(d, v.x * coeff, v.y * coeff, v.z * coeff, v.w * coeff);
}

// out[row, colOff + c] (stride DT) = src[row,:64] @ W[64x64]
// block: 256 threads -> 64 rows x 64 cols tile, 4x4 register tile per thread
__global__ void k_gemm64(int srcSel, const float* __restrict__ W,
                         int dstSel, int colOff, int N) {
    __shared__ __align__(16) float Ws[64 * 64];
    __shared__ __align__(16) float As[64 * 68];   // [k][row], padded
    const float* src = agg_ptr(srcSel);
    float* dst = feat_ptr_w(dstSel);
    int tid = threadIdx.x;
    int row0 = blockIdx.x * 64;

    for (int i = tid; i < 4096; i += 256) Ws[i] = W[i];
    for (int i = tid; i < 4096; i += 256) {
        int rr = i >> 6, k = i & 63;
        float v = (row0 + rr < N) ? src[(long)(row0 + rr) * DD + k] : 0.f;
        As[k * 68 + rr] = v;
    }
    __syncthreads();

    int cg = tid & 15, rg = tid >> 4;
    float acc[4][4];
#pragma unroll
    for (int i = 0; i < 4; i++)
#pragma unroll
        for (int j = 0; j < 4; j++) acc[i][j] = 0.f;

#pragma unroll 8
    for (int k = 0; k < 64; k++) {
        float4 a4 = *reinterpret_cast<const float4*>(&As[k * 68 + rg * 4]);
        float4 w4 = *reinterpret_cast<const float4*>(&Ws[k * 64 + cg * 4]);
        float a[4] = {a4.x, a4.y, a4.z, a4.w};
        float w[4] = {w4.x, w4.y, w4.z, w4.w};
#pragma unroll
        for (int i = 0; i < 4; i++)
#pragma unroll
            for (int j = 0; j < 4; j++) acc[i][j] += a[i] * w[j];
    }
#pragma unroll
    for (int i = 0; i < 4; i++) {
        int row = row0 + rg * 4 + i;
        if (row < N) {
            float4 o = make_float4(acc[i][0], acc[i][1], acc[i][2], acc[i][3]);
            *reinterpret_cast<float4*>(&dst[(long)row * DT + colOff + cg * 4]) = o;
        }
    }
}

// ---------------- scoring kernels ----------------
// G_r = W_r @ W_r^T  (both operands K-contiguous)
__global__ void k_G(const float* __restrict__ bW) {
    __shared__ float Asm[32 * 192];
    __shared__ float Bsm[32 * 192];
    int r = blockIdx.z;
    const float* W = bW + (long)r * DT * DT;
    int i0 = blockIdx.x * 32, j0 = blockIdx.y * 32;
    for (int t = threadIdx.x; t < 32 * 192; t += 256) {
        Asm[t] = W[(long)(i0 + t / 192) * DT + (t % 192)];
        Bsm[t] = W[(long)(j0 + t / 192) * DT + (t % 192)];
    }
    __syncthreads();
    int tj = threadIdx.x & 15, ti = threadIdx.x >> 4;
    float acc[2][2] = {{0.f, 0.f}, {0.f, 0.f}};
    for (int k = 0; k < 192; k++) {
        float a0 = Asm[(ti * 2 + 0) * 192 + k];
        float a1 = Asm[(ti * 2 + 1) * 192 + k];
        float b0 = Bsm[(tj * 2 + 0) * 192 + k];
        float b1 = Bsm[(tj * 2 + 1) * 192 + k];
        acc[0][0] += a0 * b0; acc[0][1] += a0 * b1;
        acc[1][0] += a1 * b0; acc[1][1] += a1 * b1;
    }
#pragma unroll
    for (int i = 0; i < 2; i++)
#pragma unroll
        for (int j = 0; j < 2; j++)
            g_G[r][(long)(i0 + ti * 2 + i) * DT + (j0 + tj * 2 + j)] = acc[i][j];
}

__global__ void k_score_init(float* out, int lossIdx) {
    int t = blockIdx.x * blockDim.x + threadIdx.x;
    if (t < U_NN) g_u2b[t] = -1;
    if (t < BB * DT) { g_aggsel[0][t] = 0.f; g_aggsel[1][t] = 0.f; }
    if (t == 0) out[lossIdx] = 0.f;
}

__global__ void k_scatter(const int* __restrict__ users) {
    int b = blockIdx.x * blockDim.x + threadIdx.x;
    if (b < BB) g_u2b[users[b]] = b;
}

// score2 user-side agg, filtered to batched users only
__global__ void k_edge_sel(const int* __restrict__ rows, const int* __restrict__ cols,
                           const int* __restrict__ ubd, int r) {
    int e = blockIdx.x * blockDim.x + threadIdx.x;
    if (e >= E_UI) return;
    int row = rows[e];
    int slot = g_u2b[row];
    if (slot < 0) return;
    float coeff = 1.0f / ((float)ubd[row * 2 + r] + EPSV);
    const float* s = g_Sf[r] + (long)cols[e] * DT;
    float* d = g_aggsel[r] + (long)slot * DT;
#pragma unroll
    for (int j = 0; j < 48; j++) {
        float4 v = *reinterpret_cast<const float4*>(s + j * 4);
        red_add_v4(d + j * 4, v.x * coeff, v.y * coeff, v.z * coeff, v.w * coeff);
    }
}

// z[r][b] = aggsel[r][b] @ G_r     (grid: (B, R), block 192)
__global__ void k_z() {
    __shared__ float a_s[DT];
    int b = blockIdx.x, r = blockIdx.y, c = threadIdx.x;
    a_s[c] = g_aggsel[r][(long)b * DT + c];
    __syncthreads();
    float acc = 0.f;
    for (int k = 0; k < DT; k++) acc += a_s[k] * g_G[r][(long)k * DT + c];
    g_z[r][(long)b * DT + c] = acc;
}

// bu^2 * K contribution to L2 loss (warp per b)
__global__ void k_bu_l2(const int* __restrict__ users, float* out, int lossIdx) {
    int w = (blockIdx.x * blockDim.x + threadIdx.x) >> 5;
    int lane = threadIdx.x & 31;
    if (w >= BB) return;
    int u = users[w];
    float s = 0.f;
    for (int c = lane; c < DT; c += 32) {
        float v = g_Uf[(long)u * DT + c];
        s += v * v;
    }
#pragma unroll
    for (int off = 16; off; off >>= 1) s += __shfl_down_sync(0xffffffffu, s, off);
    if (lane == 0) atomicAdd(out + lossIdx, 1e-4f * (float)KK * s);
}

// main scoring: warp per (b,k)
__global__ void k_score(const int* __restrict__ users, const int* __restrict__ items,
                        float* out, int lossIdx) {
    __shared__ float l2blk;
    if (threadIdx.x == 0) l2blk = 0.f;
    __syncthreads();
    int w = (blockIdx.x * blockDim.x + threadIdx.x) >> 5;
    int lane = threadIdx.x & 31;
    if (w < BB * KK) {
        int b = w / KK;
        int u = users[b];
        int it = items[w];
        int cb = g_u2b[u];
        float s1 = 0.f, s2a = 0.f, s2b = 0.f, l2i = 0.f;
        for (int c = lane; c < DT; c += 32) {
            float bu = g_Uf[(long)u * DT + c];
            float bi = g_If[(long)it * DT + c];
            s1 += bu * bi;
            l2i += bi * bi;
            s2a += g_z[0][(long)cb * DT + c] * g_Sf[0][(long)it * DT + c];
            s2b += g_z[1][(long)cb * DT + c] * g_Sf[1][(long)it * DT + c];
        }
#pragma unroll
        for (int off = 16; off; off >>= 1) {
            s1  += __shfl_down_sync(0xffffffffu, s1, off);
            s2a += __shfl_down_sync(0xffffffffu, s2a, off);
            s2b += __shfl_down_sync(0xffffffffu, s2b, off);
            l2i += __shfl_down_sync(0xffffffffu, l2i, off);
        }
        if (lane == 0) {
            out[w] = 0.5f * s1 + 0.25f * (s2a + s2b);
            atomicAdd(&l2blk, l2i);
        }
    }
    __syncthreads();
    if (threadIdx.x == 0) atomicAdd(out + lossIdx, 1e-4f * l2blk);
}

// ---------------- launch ----------------
extern "C" void kernel_launch(void* const* d_in, const int* in_sizes, int n_in,
                              void* d_out, int out_size) {
    const float* ue    = (const float*)d_in[0];
    const float* ie    = (const float*)d_in[1];
    const float* W_ui  = (const float*)d_in[2];   // [L,64,64]
    const float* W_ii  = (const float*)d_in[3];   // [R,L,64,64]
    const float* bW    = (const float*)d_in[4];   // [R,192,192]
    const float* mgnn  = (const float*)d_in[5];
    const int* rel_r   = (const int*)d_in[6];     // [R,E_UI]
    const int* rel_c   = (const int*)d_in[7];
    const int* tr_r    = (const int*)d_in[8];
    const int* tr_c    = (const int*)d_in[9];
    const int* ig_r    = (const int*)d_in[10];    // [R,E_II]
    const int* ig_c    = (const int*)d_in[11];
    const int* ubd     = (const int*)d_in[12];    // [U,R]
    const int* igd     = (const int*)d_in[13];    // [R,I]
    const int* users   = (const int*)d_in[14];
    const int* items   = (const int*)d_in[15];
    float* out = (float*)d_out;
    int lossIdx = out_size - 1;

    const int T = 256;
    auto g = [](long n, int t) { return (int)((n + t - 1) / t); };

    // init
    k_zero_itemcnt<<<g(I_NN, T), T>>>();
    k_coeffs<<<g(U_NN, T), T>>>(ubd, igd, mgnn);
    k_copy_emb<<<g((long)(U_NN + I_NN) * DD, T), T>>>(ue, ie);
    k_hist<<<g(E_TR, T), T>>>(tr_c);
    k_invdeg<<<g(I_NN, T), T>>>();

    // propagation layers
    for (int l = 0; l < LL; l++) {
        k_zero_layer<<<g((long)U_NN * DD + 3L * I_NN * DD, T), T>>>();
        // user <- item (per behavior, weight folded)
        for (int r = 0; r < RR; r++)
            k_edge<<<g((long)E_UI * 16, T), T>>>(rel_c + (long)r * E_UI,
                                                 rel_r + (long)r * E_UI,
                                                 E_UI, /*src If*/1, l * DD,
                                                 /*dst Uagg*/0, /*coeff*/0, r);
        // item <- user via train edges
        k_edge<<<g((long)E_TR * 16, T), T>>>(tr_r, tr_c, E_TR,
                                             /*src Uf*/0, l * DD,
                                             /*dst Iagg*/1, /*coeff*/1, 0);
        // item-item per behavior
        for (int r = 0; r < RR; r++)
            k_edge<<<g((long)E_II * 16, T), T>>>(ig_c + (long)r * E_II,
                                                 ig_r + (long)r * E_II,
                                                 E_II, /*src If*/1, l * DD,
                                                 /*dst IGagg*/2 + r, /*coeff*/2, r);
        // projections into next concat block
        k_gemm64<<<g(U_NN, 64), 256>>>(0, W_ui + (long)l * DD * DD, 0, (l + 1) * DD, U_NN);
        k_gemm64<<<g(I_NN, 64), 256>>>(1, W_ui + (long)l * DD * DD, 1, (l + 1) * DD, I_NN);
        for (int r = 0; r < RR; r++)
            k_gemm64<<<g(I_NN, 64), 256>>>(2 + r, W_ii + (long)(r * LL + l) * DD * DD,
                                           2 + r, (l + 1) * DD, I_NN);
    }

    // scoring
    {
        dim3 gg(6, 6, 2);
        k_G<<<gg, 256>>>(bW);
    }
    // NOTE: grid must cover BB*DT (98304) for the aggsel re-zero, not just U_NN.
    k_score_init<<<g((long)BB * DT, T), T>>>(out, lossIdx);
    k_scatter<<<g(BB, T), T>>>(users);
    for (int r = 0; r < RR; r++)
        k_edge_sel<<<g(E_UI, T), T>>>(rel_r + (long)r * E_UI,
                                      rel_c + (long)r * E_UI, ubd, r);
    {
        dim3 gz(BB, RR);
        k_z<<<gz, DT>>>();
    }
    k_bu_l2<<<g((long)BB * 32, T), T>>>(users, out, lossIdx);
    k_score<<<g((long)BB * KK * 32, T), T>>>(users, items, out, lossIdx);
}